// round 8
// baseline (speedup 1.0000x reference)
#include <cuda_runtime.h>
#include <cstdint>

// Problem constants (H=128 fixed by the model; E derived at launch).
#define TE       128    // edges per block
#define HH       128    // hidden H
#define HALF     64     // H/2
#define KC       16     // W1 k-chunk rows staged per iteration
#define THREADS  256

// smem: src[TE*HH] + dst[TE*HH] + w[4*KC*HH] (reused for W2 = HH*HALF = 8192)
//       + b1[HH] + b2[64] + w3[64] + idx[2*TE] ints
#define SMEM_FLOATS (2*TE*HH + 4*KC*HH + HH + 64 + 64)
#define SMEM_BYTES  (SMEM_FLOATS*4 + 2*TE*4)

__device__ __forceinline__ unsigned long long pack2(float a) {
    unsigned long long r; unsigned int u = __float_as_uint(a);
    asm("mov.b64 %0, {%1, %1};" : "=l"(r) : "r"(u));
    return r;
}
__device__ __forceinline__ void fma2(unsigned long long& d,
                                     unsigned long long a, unsigned long long b) {
    asm("fma.rn.f32x2 %0, %1, %2, %0;" : "+l"(d) : "l"(a), "l"(b));
}
__device__ __forceinline__ float lo32(unsigned long long v) { return __uint_as_float((unsigned int)v); }
__device__ __forceinline__ float hi32(unsigned long long v) { return __uint_as_float((unsigned int)(v >> 32)); }

__global__ void __launch_bounds__(THREADS, 1)
linkpred_kernel(const float* __restrict__ z,
                const int* __restrict__ ei,        // int32: JAX x64-disabled makes "int64" edge_index int32
                const float* __restrict__ W1, const float* __restrict__ b1,
                const float* __restrict__ W2, const float* __restrict__ b2,
                const float* __restrict__ W3, const float* __restrict__ b3,
                float* __restrict__ out, int E, int n_nodes)
{
    extern __shared__ float smem[];
    float* s_src = smem;                       // TE*HH   (reused as h1 later)
    float* s_dst = s_src + TE*HH;              // TE*HH
    float* s_w   = s_dst + TE*HH;              // 4*KC*HH (== HH*HALF for W2 reuse)
    float* s_b1  = s_w + 4*KC*HH;              // HH
    float* s_b2  = s_b1 + HH;                  // 64
    float* s_w3  = s_b2 + 64;                  // 64
    int*   s_idx = (int*)(s_w3 + 64);          // 2*TE

    const int tid = threadIdx.x;
    const long long e0g = (long long)blockIdx.x * TE;

    // ---- stage edge indices (clamped for tail block + defensive range clamp) ----
    if (tid < TE) {
        long long e = e0g + tid;
        int si = 0, di = 0;
        if (e < (long long)E) { si = ei[e]; di = ei[(long long)E + e]; }
        // Defensive clamp: a bad index becomes a wrong (checkable) answer, not a crash.
        si = min(max(si, 0), n_nodes - 1);
        di = min(max(di, 0), n_nodes - 1);
        s_idx[tid]      = si;
        s_idx[TE + tid] = di;
    }
    if (tid < HH)                       s_b1[tid]          = b1[tid];
    else if (tid < HH + 64)             s_b2[tid - HH]     = b2[tid - HH];
    else if (tid < HH + 128)            s_w3[tid - HH - 64] = W3[tid - HH - 64];
    __syncthreads();

    // ---- gather: copy z rows for src/dst (coalesced float4) ----
    {
        const float4* z4 = (const float4*)z;
        float4* s4 = (float4*)s_src;
        float4* d4 = (float4*)s_dst;
        for (int t = tid; t < TE*(HH/4); t += THREADS) {
            int e = t >> 5;          // HH/4 = 32 float4 per row
            int q = t & 31;
            s4[t] = z4[(long long)s_idx[e]      * (HH/4) + q];
            d4[t] = z4[(long long)s_idx[TE + e] * (HH/4) + q];
        }
    }
    __syncthreads();

    // ---- GEMM1: h1[128e,128] = [src|dst|src*dst|abs(src-dst)] @ W1 ----
    const int ct = tid & 15;           // 16 column groups of 8
    const int et = tid >> 4;           // 16 edge groups of 8
    const int j0 = ct * 8;
    const float* srcBase = s_src + et * 8 * HH;
    const float* dstBase = s_dst + et * 8 * HH;

    unsigned long long acc[8][4];
    #pragma unroll
    for (int i = 0; i < 8; i++)
        #pragma unroll
        for (int q = 0; q < 4; q++) acc[i][q] = 0ull;

    for (int kc = 0; kc < HH; kc += KC) {
        __syncthreads();  // previous chunk fully consumed
        // stage W1 chunk: layout s_w[p][kk][j], p=part (src/dst/inter/diff)
        {
            const float4* W1g4 = (const float4*)W1;
            float4* s_w4 = (float4*)s_w;
            #pragma unroll
            for (int i = 0; i < 8; i++) {
                int f4  = tid + i * THREADS;      // 0..2047
                int j4  = f4 & 31;
                int row = f4 >> 5;                // 0..63
                int p   = row >> 4;
                int kk  = row & 15;
                s_w4[f4] = W1g4[(p * HH + kc + kk) * (HH/4) + j4];
            }
        }
        __syncthreads();

        #pragma unroll
        for (int kk = 0; kk < KC; kk++) {
            const int k = kc + kk;
            // W rows for the 4 parts, 8 cols each = 2x ulonglong2 (4 f32x2 pairs)
            ulonglong2 w[4][2];
            #pragma unroll
            for (int p = 0; p < 4; p++) {
                const ulonglong2* wp =
                    (const ulonglong2*)(s_w + (p * KC + kk) * HH + j0);
                w[p][0] = wp[0];
                w[p][1] = wp[1];
            }
            #pragma unroll
            for (int i = 0; i < 8; i++) {
                float s = srcBase[i * HH + k];    // broadcast LDS (uniform in 16-lane group)
                float d = dstBase[i * HH + k];
                unsigned long long ap[4];
                ap[0] = pack2(s);
                ap[1] = pack2(d);
                ap[2] = pack2(s * d);
                ap[3] = pack2(fabsf(s - d));
                #pragma unroll
                for (int p = 0; p < 4; p++) {
                    fma2(acc[i][0], ap[p], w[p][0].x);
                    fma2(acc[i][1], ap[p], w[p][0].y);
                    fma2(acc[i][2], ap[p], w[p][1].x);
                    fma2(acc[i][3], ap[p], w[p][1].y);
                }
            }
        }
    }
    __syncthreads();  // done reading s_src/s_dst and s_w

    // ---- epilogue1: h1 = relu(acc + b1) -> s_src region; stage W2 -> s_w ----
    float* s_h1 = s_src;
    #pragma unroll
    for (int i = 0; i < 8; i++) {
        int e = et * 8 + i;
        #pragma unroll
        for (int q = 0; q < 4; q++) {
            int j = j0 + q * 2;
            float2 v;
            v.x = fmaxf(lo32(acc[i][q]) + s_b1[j],     0.0f);
            v.y = fmaxf(hi32(acc[i][q]) + s_b1[j + 1], 0.0f);
            *(float2*)&s_h1[e * HH + j] = v;
        }
    }
    {
        const float4* W2g4 = (const float4*)W2;   // HH*HALF = 8192 floats = 2048 float4
        float4* s_w4 = (float4*)s_w;
        #pragma unroll
        for (int i = 0; i < 8; i++) s_w4[tid + i * THREADS] = W2g4[tid + i * THREADS];
    }
    __syncthreads();

    // ---- GEMM2: h2[128e,64] = h1 @ W2 ----
    const int c0 = ct * 4;  // 16 groups x 4 cols = 64
    unsigned long long acc2[8][2];
    #pragma unroll
    for (int i = 0; i < 8; i++) { acc2[i][0] = 0ull; acc2[i][1] = 0ull; }

    #pragma unroll 4
    for (int k = 0; k < HH; k++) {
        ulonglong2 wv = *(const ulonglong2*)(s_w + k * HALF + c0);
        #pragma unroll
        for (int i = 0; i < 8; i++) {
            unsigned long long a = pack2(s_h1[(et * 8 + i) * HH + k]);
            fma2(acc2[i][0], a, wv.x);
            fma2(acc2[i][1], a, wv.y);
        }
    }

    // ---- epilogue2: relu(h2 + b2) . W3, reduce over 16 col-group lanes ----
    const float b3v = b3[0];
    #pragma unroll
    for (int i = 0; i < 8; i++) {
        float partial = 0.0f;
        #pragma unroll
        for (int q = 0; q < 2; q++) {
            int c = c0 + q * 2;
            float a0 = fmaxf(lo32(acc2[i][q]) + s_b2[c],     0.0f);
            float a1 = fmaxf(hi32(acc2[i][q]) + s_b2[c + 1], 0.0f);
            partial += a0 * s_w3[c] + a1 * s_w3[c + 1];
        }
        partial += __shfl_down_sync(0xffffffffu, partial, 8, 16);
        partial += __shfl_down_sync(0xffffffffu, partial, 4, 16);
        partial += __shfl_down_sync(0xffffffffu, partial, 2, 16);
        partial += __shfl_down_sync(0xffffffffu, partial, 1, 16);
        if (ct == 0) {
            long long e = e0g + et * 8 + i;
            if (e < (long long)E) out[e] = partial + b3v;
        }
    }
}

extern "C" void kernel_launch(void* const* d_in, const int* in_sizes, int n_in,
                              void* d_out, int out_size)
{
    const float* z  = (const float*)d_in[0];
    const int*   ei = (const int*)d_in[1];     // int32 on the wire (JAX x64 disabled)
    const float* W1 = (const float*)d_in[2];
    const float* b1 = (const float*)d_in[3];
    const float* W2 = (const float*)d_in[4];
    const float* b2 = (const float*)d_in[5];
    const float* W3 = (const float*)d_in[6];
    const float* b3 = (const float*)d_in[7];
    float* out = (float*)d_out;

    const int E = out_size;                    // out is score[E]
    const int n_nodes = in_sizes[0] / HH;      // z is [n_nodes, 128]
    if (E <= 0 || n_nodes <= 0) return;

    cudaFuncSetAttribute(linkpred_kernel,
                         cudaFuncAttributeMaxDynamicSharedMemorySize, SMEM_BYTES);
    const int grid = (E + TE - 1) / TE;
    linkpred_kernel<<<grid, THREADS, SMEM_BYTES>>>(z, ei, W1, b1, W2, b2, W3, b3,
                                                   out, E, n_nodes);
}

// round 15
// speedup vs baseline: 1.4317x; 1.4317x over previous
#include <cuda_runtime.h>
#include <cstdint>

// Problem constants (H=128 fixed by the model; E derived at launch).
#define TE       128    // edges per block
#define HH       128    // hidden H
#define HALF     64     // H/2
#define KC       16     // W1 k-chunk rows staged per iteration
#define THREADS  512
#define EPT      4      // edges per thread (32 edge groups x 16 col groups)

// smem: src[TE*HH] + dst[TE*HH] + w[4*KC*HH] (reused for W2 = HH*HALF = 8192)
//       + b1[HH] + b2[64] + w3[64] + idx[2*TE] ints
#define SMEM_FLOATS (2*TE*HH + 4*KC*HH + HH + 64 + 64)
#define SMEM_BYTES  (SMEM_FLOATS*4 + 2*TE*4)

__device__ __forceinline__ unsigned long long pack2(float a) {
    unsigned long long r; unsigned int u = __float_as_uint(a);
    asm("mov.b64 %0, {%1, %1};" : "=l"(r) : "r"(u));
    return r;
}
__device__ __forceinline__ void fma2(unsigned long long& d,
                                     unsigned long long a, unsigned long long b) {
    asm("fma.rn.f32x2 %0, %1, %2, %0;" : "+l"(d) : "l"(a), "l"(b));
}
__device__ __forceinline__ float lo32(unsigned long long v) { return __uint_as_float((unsigned int)v); }
__device__ __forceinline__ float hi32(unsigned long long v) { return __uint_as_float((unsigned int)(v >> 32)); }

__global__ void __launch_bounds__(THREADS, 1)
linkpred_kernel(const float* __restrict__ z,
                const int* __restrict__ ei,        // int32 on the wire (JAX x64 disabled)
                const float* __restrict__ W1, const float* __restrict__ b1,
                const float* __restrict__ W2, const float* __restrict__ b2,
                const float* __restrict__ W3, const float* __restrict__ b3,
                float* __restrict__ out, int E, int n_nodes)
{
    extern __shared__ float smem[];
    float* s_src = smem;                       // TE*HH   (reused as h1 later)
    float* s_dst = s_src + TE*HH;              // TE*HH
    float* s_w   = s_dst + TE*HH;              // 4*KC*HH (== HH*HALF for W2 reuse)
    float* s_b1  = s_w + 4*KC*HH;              // HH
    float* s_b2  = s_b1 + HH;                  // 64
    float* s_w3  = s_b2 + 64;                  // 64
    int*   s_idx = (int*)(s_w3 + 64);          // 2*TE

    const int tid = threadIdx.x;
    const long long e0g = (long long)blockIdx.x * TE;

    // ---- stage edge indices (tail clamp + defensive range clamp) ----
    if (tid < TE) {
        long long e = e0g + tid;
        int si = 0, di = 0;
        if (e < (long long)E) { si = ei[e]; di = ei[(long long)E + e]; }
        si = min(max(si, 0), n_nodes - 1);
        di = min(max(di, 0), n_nodes - 1);
        s_idx[tid]      = si;
        s_idx[TE + tid] = di;
    }
    if (tid < HH)                        s_b1[tid]           = b1[tid];
    else if (tid < HH + 64)              s_b2[tid - HH]      = b2[tid - HH];
    else if (tid < HH + 128)             s_w3[tid - HH - 64] = W3[tid - HH - 64];
    __syncthreads();

    // ---- gather: copy z rows for src/dst (coalesced float4) ----
    {
        const float4* z4 = (const float4*)z;
        float4* s4 = (float4*)s_src;
        float4* d4 = (float4*)s_dst;
        #pragma unroll
        for (int r = 0; r < TE*(HH/4)/THREADS; r++) {
            int t = tid + r * THREADS;
            int e = t >> 5;          // HH/4 = 32 float4 per row
            int q = t & 31;
            s4[t] = z4[(long long)s_idx[e]      * (HH/4) + q];
            d4[t] = z4[(long long)s_idx[TE + e] * (HH/4) + q];
        }
    }
    __syncthreads();

    // ---- GEMM1: h1[128e,128] = [src|dst|src*dst|abs(src-dst)] @ W1 ----
    const int ct = tid & 15;           // 16 column groups of 8
    const int et = tid >> 4;           // 32 edge groups of EPT=4
    const int j0 = ct * 8;
    const float* srcBase = s_src + et * EPT * HH;
    const float* dstBase = s_dst + et * EPT * HH;

    unsigned long long acc[EPT][4];
    #pragma unroll
    for (int i = 0; i < EPT; i++)
        #pragma unroll
        for (int q = 0; q < 4; q++) acc[i][q] = 0ull;

    for (int kc = 0; kc < HH; kc += KC) {
        __syncthreads();  // previous chunk fully consumed
        // stage W1 chunk: layout s_w[p][kk][j], p=part (src/dst/inter/diff)
        {
            const float4* W1g4 = (const float4*)W1;
            float4* s_w4 = (float4*)s_w;
            #pragma unroll
            for (int i = 0; i < 4; i++) {
                int f4  = tid + i * THREADS;      // 0..2047
                int j4  = f4 & 31;
                int row = f4 >> 5;                // 0..63
                int p   = row >> 4;
                int kk  = row & 15;
                s_w4[f4] = W1g4[(p * HH + kc + kk) * (HH/4) + j4];
            }
        }
        __syncthreads();

        #pragma unroll
        for (int kk = 0; kk < KC; kk++) {
            const int k = kc + kk;
            ulonglong2 w[4][2];
            #pragma unroll
            for (int p = 0; p < 4; p++) {
                const ulonglong2* wp =
                    (const ulonglong2*)(s_w + (p * KC + kk) * HH + j0);
                w[p][0] = wp[0];
                w[p][1] = wp[1];
            }
            #pragma unroll
            for (int i = 0; i < EPT; i++) {
                float s = srcBase[i * HH + k];    // broadcast LDS (uniform in 16-lane group)
                float d = dstBase[i * HH + k];
                unsigned long long ap[4];
                ap[0] = pack2(s);
                ap[1] = pack2(d);
                ap[2] = pack2(s * d);
                ap[3] = pack2(fabsf(s - d));
                #pragma unroll
                for (int p = 0; p < 4; p++) {
                    fma2(acc[i][0], ap[p], w[p][0].x);
                    fma2(acc[i][1], ap[p], w[p][0].y);
                    fma2(acc[i][2], ap[p], w[p][1].x);
                    fma2(acc[i][3], ap[p], w[p][1].y);
                }
            }
        }
    }
    __syncthreads();  // done reading s_src/s_dst and s_w

    // ---- epilogue1: h1 = relu(acc + b1) -> s_src region; stage W2 -> s_w ----
    float* s_h1 = s_src;
    #pragma unroll
    for (int i = 0; i < EPT; i++) {
        int e = et * EPT + i;
        #pragma unroll
        for (int q = 0; q < 4; q++) {
            int j = j0 + q * 2;
            float2 v;
            v.x = fmaxf(lo32(acc[i][q]) + s_b1[j],     0.0f);
            v.y = fmaxf(hi32(acc[i][q]) + s_b1[j + 1], 0.0f);
            *(float2*)&s_h1[e * HH + j] = v;
        }
    }
    {
        const float4* W2g4 = (const float4*)W2;   // HH*HALF = 8192 floats = 2048 float4
        float4* s_w4 = (float4*)s_w;
        #pragma unroll
        for (int i = 0; i < 4; i++) s_w4[tid + i * THREADS] = W2g4[tid + i * THREADS];
    }
    __syncthreads();

    // ---- GEMM2: h2[128e,64] = h1 @ W2 ----
    const int c0 = ct * 4;  // 16 groups x 4 cols = 64
    unsigned long long acc2[EPT][2];
    #pragma unroll
    for (int i = 0; i < EPT; i++) { acc2[i][0] = 0ull; acc2[i][1] = 0ull; }

    #pragma unroll 4
    for (int k = 0; k < HH; k++) {
        ulonglong2 wv = *(const ulonglong2*)(s_w + k * HALF + c0);
        #pragma unroll
        for (int i = 0; i < EPT; i++) {
            unsigned long long a = pack2(s_h1[(et * EPT + i) * HH + k]);
            fma2(acc2[i][0], a, wv.x);
            fma2(acc2[i][1], a, wv.y);
        }
    }

    // ---- epilogue2: relu(h2 + b2) . W3, reduce over 16 col-group lanes ----
    const float b3v = b3[0];
    #pragma unroll
    for (int i = 0; i < EPT; i++) {
        float partial = 0.0f;
        #pragma unroll
        for (int q = 0; q < 2; q++) {
            int c = c0 + q * 2;
            float a0 = fmaxf(lo32(acc2[i][q]) + s_b2[c],     0.0f);
            float a1 = fmaxf(hi32(acc2[i][q]) + s_b2[c + 1], 0.0f);
            partial += a0 * s_w3[c] + a1 * s_w3[c + 1];
        }
        partial += __shfl_down_sync(0xffffffffu, partial, 8, 16);
        partial += __shfl_down_sync(0xffffffffu, partial, 4, 16);
        partial += __shfl_down_sync(0xffffffffu, partial, 2, 16);
        partial += __shfl_down_sync(0xffffffffu, partial, 1, 16);
        if (ct == 0) {
            long long e = e0g + et * EPT + i;
            if (e < (long long)E) out[e] = partial + b3v;
        }
    }
}

extern "C" void kernel_launch(void* const* d_in, const int* in_sizes, int n_in,
                              void* d_out, int out_size)
{
    const float* z  = (const float*)d_in[0];
    const int*   ei = (const int*)d_in[1];     // int32 on the wire (JAX x64 disabled)
    const float* W1 = (const float*)d_in[2];
    const float* b1 = (const float*)d_in[3];
    const float* W2 = (const float*)d_in[4];
    const float* b2 = (const float*)d_in[5];
    const float* W3 = (const float*)d_in[6];
    const float* b3 = (const float*)d_in[7];
    float* out = (float*)d_out;

    const int E = out_size;                    // out is score[E]
    const int n_nodes = in_sizes[0] / HH;      // z is [n_nodes, 128]
    if (E <= 0 || n_nodes <= 0) return;

    cudaFuncSetAttribute(linkpred_kernel,
                         cudaFuncAttributeMaxDynamicSharedMemorySize, SMEM_BYTES);
    const int grid = (E + TE - 1) / TE;
    linkpred_kernel<<<grid, THREADS, SMEM_BYTES>>>(z, ei, W1, b1, W2, b2, W3, b3,
                                                   out, E, n_nodes);
}